// round 1
// baseline (speedup 1.0000x reference)
#include <cuda_runtime.h>

// KL( N(mu1, diag(v1)) || N(mu2, diag(v2)) ) averaged over B rows.
// result = (1/B) * sum_rows 0.5*( sum(log v2 - log v1) - N + sum(v1/v2) + sum(d^2/v2) )
//        = 0.5 * S / B - 0.5*N,   with S = sum over all B*N elements of
//          [ ln(v2) - ln(v1) + (v1 + d^2) * (1/v2) ]
// B = 16384, N = 1024  ->  result = 0.5*S/16384 - 512.

static __device__ __forceinline__ float fast_rcp(float x) {
    float r; asm("rcp.approx.f32 %0, %1;" : "=f"(r) : "f"(x)); return r;
}
static __device__ __forceinline__ float fast_lg2(float x) {
    float r; asm("lg2.approx.f32 %0, %1;" : "=f"(r) : "f"(x)); return r;
}

__global__ void kl_init(float* __restrict__ out) {
    // Seed with -0.5*N so the main kernel only has to accumulate 0.5*S/B.
    out[0] = -512.0f;
}

__global__ void __launch_bounds__(256) kl_main(
    const float4* __restrict__ mu1,
    const float4* __restrict__ mu2,
    const float4* __restrict__ v1,
    const float4* __restrict__ v2,
    float* __restrict__ out,
    int n4)
{
    float acc  = 0.0f;   // sum of (v1 + d^2) * rcp(v2)
    float accl = 0.0f;   // sum of lg2(v2) - lg2(v1); multiply by ln(2) once at end

    const int stride = gridDim.x * blockDim.x;
    for (int i = blockIdx.x * blockDim.x + threadIdx.x; i < n4; i += stride) {
        const float4 a = mu1[i];
        const float4 b = mu2[i];
        const float4 x = v1[i];
        const float4 y = v2[i];

        float d, ry;
        d = b.x - a.x; ry = fast_rcp(y.x);
        acc  = fmaf(fmaf(d, d, x.x), ry, acc);
        accl += fast_lg2(y.x) - fast_lg2(x.x);

        d = b.y - a.y; ry = fast_rcp(y.y);
        acc  = fmaf(fmaf(d, d, x.y), ry, acc);
        accl += fast_lg2(y.y) - fast_lg2(x.y);

        d = b.z - a.z; ry = fast_rcp(y.z);
        acc  = fmaf(fmaf(d, d, x.z), ry, acc);
        accl += fast_lg2(y.z) - fast_lg2(x.z);

        d = b.w - a.w; ry = fast_rcp(y.w);
        acc  = fmaf(fmaf(d, d, x.w), ry, acc);
        accl += fast_lg2(y.w) - fast_lg2(x.w);
    }

    // fold ln-domain term: ln = lg2 * ln(2)
    acc = fmaf(0.693147180559945f, accl, acc);

    // Warp reduce
    #pragma unroll
    for (int o = 16; o > 0; o >>= 1)
        acc += __shfl_xor_sync(0xffffffffu, acc, o);

    __shared__ float ws[8];
    const int lane = threadIdx.x & 31;
    const int warp = threadIdx.x >> 5;
    if (lane == 0) ws[warp] = acc;
    __syncthreads();

    if (warp == 0) {
        acc = (lane < 8) ? ws[lane] : 0.0f;
        #pragma unroll
        for (int o = 4; o > 0; o >>= 1)
            acc += __shfl_xor_sync(0xffffffffu, acc, o);
        if (lane == 0)
            atomicAdd(out, acc * (0.5f / 16384.0f));
    }
}

extern "C" void kernel_launch(void* const* d_in, const int* in_sizes, int n_in,
                              void* d_out, int out_size)
{
    const float4* mu1 = (const float4*)d_in[0];
    const float4* mu2 = (const float4*)d_in[1];
    const float4* v1  = (const float4*)d_in[2];
    const float4* v2  = (const float4*)d_in[3];
    float* out = (float*)d_out;

    const int n  = in_sizes[0];     // 16384 * 1024
    const int n4 = n >> 2;          // float4 count

    kl_init<<<1, 1>>>(out);
    // 148 SMs * 8 blocks = 1184 blocks of 256 threads -> ~303K threads,
    // ~14 float4 iterations each, MLP=4 LDG.128 per iteration.
    kl_main<<<1184, 256>>>(mu1, mu2, v1, v2, out, n4);
}